// round 15
// baseline (speedup 1.0000x reference)
#include <cuda_runtime.h>
#include <cstdint>
#include <cstddef>

#define BATCH  8192
#define DIN    784
#define HID    1200
#define DOUT   10
#define TSTEPS 35

#define NC1    128
#define KH1    392          // layer1 K staged in 2 halves
#define NC2    128
#define KS2    400          // layer2 K staged in 3 stages
// sparse layer-2 selected when total nnz < BATCH * NNZ_THRESH_PER_ROW
#define NNZ_THRESH_PER_ROW 640

// ---------------- device state (no allocs allowed) ----------------
__device__ float g_mem1[(size_t)BATCH * HID];
__device__ float g_sum1[(size_t)BATCH * HID];
__device__ float g_mem2[(size_t)BATCH * HID];
__device__ float g_sum2[(size_t)BATCH * HID];
__device__ float g_mem3[(size_t)BATCH * DOUT];
__device__ float g_sum3[(size_t)BATCH * DOUT];
__device__ float g_W1T[(size_t)DIN * HID];            // W1 transposed: [k][n]
__device__ float g_W2T[(size_t)HID * HID];            // W2 transposed: [k][n]
__device__ uint16_t g_idx[(size_t)BATCH * DIN];       // layer1 spike indices (ascending)
__device__ int g_cnt[BATCH];
__device__ int g_cntlo1[BATCH];                       // count with k < KH1
__device__ uint16_t g_idx2[(size_t)BATCH * HID];      // layer2 nonzero indices (ascending)
__device__ float g_val2[(size_t)BATCH * HID];         // layer2 nonzero values
__device__ int g_cnt2[BATCH];                         // total
__device__ int g_cnt2a[BATCH];                        // count with k < KS2
__device__ int g_cnt2b[BATCH];                        // count with k < 2*KS2
__device__ float g_part[(size_t)BATCH * HID];         // stage-crossing accumulators
__device__ int g_nnz_total;
__device__ int g_mode;                                // 1 = sparse layer2, 0 = dense

// ---------------- packed f32x2 helpers ----------------
__device__ __forceinline__ void fma2(unsigned long long& acc,
                                     unsigned long long a2, unsigned long long b2) {
    asm("fma.rn.f32x2 %0, %1, %2, %0;" : "+l"(acc) : "l"(a2), "l"(b2));
}
__device__ __forceinline__ unsigned long long bcast2(float v) {
    unsigned long long r;
    asm("mov.b64 %0, {%1, %1};" : "=l"(r) : "r"(__float_as_uint(v)));
    return r;
}
__device__ __forceinline__ float lo32(unsigned long long p) {
    return __uint_as_float((uint32_t)p);
}
__device__ __forceinline__ float hi32(unsigned long long p) {
    return __uint_as_float((uint32_t)(p >> 32));
}

// ---------------- Threefry-2x32 (exact JAX semantics) ----------------
__host__ __device__ __forceinline__ uint32_t rotl32(uint32_t v, int r) {
#ifdef __CUDA_ARCH__
    return __funnelshift_l(v, v, r);
#else
    return (v << r) | (v >> (32 - r));
#endif
}

__host__ __device__ __forceinline__ void threefry2x32(
    uint32_t k0, uint32_t k1, uint32_t x0, uint32_t x1,
    uint32_t& o0, uint32_t& o1)
{
    uint32_t ks2 = k0 ^ k1 ^ 0x1BD11BDAu;
    x0 += k0; x1 += k1;
#define TF_R(r) { x0 += x1; x1 = rotl32(x1, (r)); x1 ^= x0; }
    TF_R(13) TF_R(15) TF_R(26) TF_R(6)
    x0 += k1;  x1 += ks2 + 1u;
    TF_R(17) TF_R(29) TF_R(16) TF_R(24)
    x0 += ks2; x1 += k0 + 2u;
    TF_R(13) TF_R(15) TF_R(26) TF_R(6)
    x0 += k0;  x1 += k1 + 3u;
    TF_R(17) TF_R(29) TF_R(16) TF_R(24)
    x0 += k1;  x1 += ks2 + 4u;
    TF_R(13) TF_R(15) TF_R(26) TF_R(6)
    x0 += ks2; x1 += k0 + 5u;
#undef TF_R
    o0 = x0; o1 = x1;
}

__device__ __forceinline__ unsigned losplit_mask(int base, int S) {
    return (base + 32 <= S) ? 0xffffffffu
         : (base >= S ? 0u : ((1u << (S - base)) - 1u));
}

// ---------------- kernels ----------------
__global__ void zero_state_kernel() {
    size_t i = (size_t)blockIdx.x * blockDim.x + threadIdx.x;
    size_t stride = (size_t)gridDim.x * blockDim.x;
    size_t total = (size_t)BATCH * HID;
    for (size_t p = i; p < total; p += stride) {
        g_mem1[p] = 0.f; g_sum1[p] = 0.f;
        g_mem2[p] = 0.f; g_sum2[p] = 0.f;
    }
    if (i < (size_t)BATCH * DOUT) { g_mem3[i] = 0.f; g_sum3[i] = 0.f; }
    if (i == 0) { g_nnz_total = 0; g_mode = 0; }
}

__global__ void transpose_w1_kernel(const float* __restrict__ W1) {
    int idx = blockIdx.x * blockDim.x + threadIdx.x;
    if (idx >= DIN * HID) return;
    int k = idx / HID, n = idx - k * HID;
    g_W1T[idx] = W1[(size_t)n * DIN + k];
}

__global__ void transpose_w2_kernel(const float* __restrict__ W2) {
    int idx = blockIdx.x * blockDim.x + threadIdx.x;
    if (idx >= HID * HID) return;
    int k = idx / HID, n = idx - k * HID;
    g_W2T[idx] = W2[(size_t)n * HID + k];
}

// Spike gen + per-row compaction (ascending k) + split count at KH1.
__global__ __launch_bounds__(256) void spike_compact_kernel(
    const float* __restrict__ x, uint32_t kt0, uint32_t kt1)
{
    int warp = (blockIdx.x * blockDim.x + threadIdx.x) >> 5;
    int lane = threadIdx.x & 31;
    if (warp >= BATCH) return;
    const float* xr = x + (size_t)warp * DIN;
    uint16_t* outp = g_idx + (size_t)warp * DIN;
    int cnt = 0, cntlo = 0;
    for (int base = 0; base < DIN; base += 32) {
        int k = base + lane;
        bool p = false;
        if (k < DIN) {
            uint32_t i = (uint32_t)(warp * DIN + k);
            uint32_t y0, y1;
            threefry2x32(kt0, kt1, 0u, i, y0, y1);
            uint32_t bits = y0 ^ y1;
            uint32_t fb = (bits >> 9) | 0x3f800000u;
            float u = __uint_as_float(fb) - 1.0f;
            p = (u * 5.0f <= xr[k]);
        }
        unsigned mask = __ballot_sync(0xffffffffu, p);
        if (p) outp[cnt + __popc(mask & ((1u << lane) - 1))] = (uint16_t)k;
        cnt += __popc(mask);
        cntlo += __popc(mask & losplit_mask(base, KH1));
    }
    if (lane == 0) { g_cnt[warp] = cnt; g_cntlo1[warp] = cntlo; }
}

// Layer 1 sparse: warp-per-row broadcast, 4 cols/lane (LDS.128), K in two
// smem halves. Per-column ascending-k RN chain (fma(1,w,acc)==RN(w+acc));
// chain crosses halves via g_part as raw u64 bits -> bit-exact.
__global__ __launch_bounds__(512, 1) void layer1_sparse_kernel(
    float* __restrict__ mem, float* __restrict__ spksum)
{
    extern __shared__ float sW[];   // KH1 * NC1 floats (200704 B)
    const int tid = threadIdx.x;
    const int c0 = blockIdx.y * NC1;
    const int wrp  = tid >> 5;
    const int lane = tid & 31;
    const int c = c0 + lane * 4;
    const bool valid = (c < HID);
    const unsigned long long ones = 0x3f8000003f800000ull;

    for (int h = 0; h < 2; h++) {
        const int k0 = h * KH1;
        __syncthreads();
        for (int idx = tid; idx < KH1 * (NC1 / 4); idx += 512) {
            int k = idx / (NC1 / 4), q = idx - k * (NC1 / 4);
            int cc = c0 + q * 4;
            float4 v = make_float4(0.f, 0.f, 0.f, 0.f);
            if (cc + 3 < HID)
                v = *reinterpret_cast<const float4*>(
                    &g_W1T[(size_t)(k0 + k) * HID + cc]);
            *reinterpret_cast<float4*>(&sW[k * NC1 + q * 4]) = v;
        }
        __syncthreads();

        for (int rl = 0; rl < 32; rl++) {
            const int row = blockIdx.x * 512 + wrp * 32 + rl;
            const int ib = h ? g_cntlo1[row] : 0;
            const int ie = h ? g_cnt[row] : g_cntlo1[row];
            const uint16_t* il = g_idx + (size_t)row * DIN;
            const size_t base = (size_t)row * HID + c;

            ulonglong2 acc = make_ulonglong2(0ull, 0ull);
            if (h == 1 && valid)
                acc = *reinterpret_cast<ulonglong2*>(g_part + base);

            if (ie > ib) {
                int k1 = il[ib] - k0;
                ulonglong2 w = *reinterpret_cast<const ulonglong2*>(
                    &sW[k1 * NC1 + lane * 4]);
                for (int i = ib; i < ie; i++) {
                    int inext = (i + 1 < ie) ? (i + 1) : (ie - 1);
                    int k2 = il[inext] - k0;
                    ulonglong2 wn = *reinterpret_cast<const ulonglong2*>(
                        &sW[k2 * NC1 + lane * 4]);
                    fma2(acc.x, w.x, ones);
                    fma2(acc.y, w.y, ones);
                    w = wn;
                }
            }

            if (h == 0) {
                if (valid)
                    *reinterpret_cast<ulonglong2*>(g_part + base) = acc;
            } else if (valid) {
                float4 m = *reinterpret_cast<float4*>(mem + base);
                float4 sv = *reinterpret_cast<float4*>(spksum + base);
                float av[4] = { lo32(acc.x), hi32(acc.x), lo32(acc.y), hi32(acc.y) };
                float* mp = &m.x; float* sp = &sv.x;
#pragma unroll
                for (int e = 0; e < 4; e++) {
                    float v = mp[e] + av[e];
                    bool s = (v >= 1.0f);
                    mp[e] = s ? 0.0f : v;
                    if (s) sp[e] += 1.0f;
                }
                *reinterpret_cast<float4*>(mem + base) = m;
                *reinterpret_cast<float4*>(spksum + base) = sv;
            }
        }
    }
}

// Compact nonzeros of sum1 per row (ascending k) + prefix counts at stage
// boundaries + global nnz tally.
__global__ __launch_bounds__(256) void compact2_kernel() {
    int warp = (blockIdx.x * blockDim.x + threadIdx.x) >> 5;
    int lane = threadIdx.x & 31;
    if (warp >= BATCH) return;
    const float* sr = g_sum1 + (size_t)warp * HID;
    uint16_t* outi = g_idx2 + (size_t)warp * HID;
    float* outv = g_val2 + (size_t)warp * HID;
    int cnt = 0, ca = 0, cb = 0;
    for (int base = 0; base < HID; base += 32) {
        int k = base + lane;
        float v = (k < HID) ? sr[k] : 0.f;
        bool p = (v != 0.f);
        unsigned mask = __ballot_sync(0xffffffffu, p);
        if (p) {
            int pos = cnt + __popc(mask & ((1u << lane) - 1));
            outi[pos] = (uint16_t)k;
            outv[pos] = v;
        }
        cnt += __popc(mask);
        ca += __popc(mask & losplit_mask(base, KS2));
        cb += __popc(mask & losplit_mask(base, 2 * KS2));
    }
    if (lane == 0) {
        g_cnt2[warp] = cnt; g_cnt2a[warp] = ca; g_cnt2b[warp] = cb;
        atomicAdd(&g_nnz_total, cnt);
    }
}

__global__ void set_mode_kernel() {
    g_mode = (g_nnz_total < BATCH * NNZ_THRESH_PER_ROW) ? 1 : 0;
    g_nnz_total = 0;
}

// Layer 2 sparse (mode 1): warp-per-row, 4 cols/lane, K in three smem stages.
// Skips exact zeros of sum1 in ascending k -> bit-identical chain to dense.
__global__ __launch_bounds__(512, 1) void layer2_sparse_kernel(
    float* __restrict__ mem, float* __restrict__ spksum)
{
    if (g_mode != 1) return;
    extern __shared__ float sW2[];   // KS2 * NC2 floats (204800 B)
    const int tid = threadIdx.x;
    const int c0 = blockIdx.y * NC2;
    const int wrp  = tid >> 5;
    const int lane = tid & 31;
    const int c = c0 + lane * 4;
    const bool valid = (c < HID);

    for (int h = 0; h < 3; h++) {
        const int k0 = h * KS2;
        __syncthreads();
        for (int idx = tid; idx < KS2 * (NC2 / 4); idx += 512) {
            int k = idx / (NC2 / 4), q = idx - k * (NC2 / 4);
            int cc = c0 + q * 4;
            float4 v = make_float4(0.f, 0.f, 0.f, 0.f);
            if (cc + 3 < HID)
                v = *reinterpret_cast<const float4*>(
                    &g_W2T[(size_t)(k0 + k) * HID + cc]);
            *reinterpret_cast<float4*>(&sW2[k * NC2 + q * 4]) = v;
        }
        __syncthreads();

        for (int rl = 0; rl < 32; rl++) {
            const int row = blockIdx.x * 512 + wrp * 32 + rl;
            const int ib = (h == 0) ? 0 : (h == 1 ? g_cnt2a[row] : g_cnt2b[row]);
            const int ie = (h == 0) ? g_cnt2a[row] : (h == 1 ? g_cnt2b[row] : g_cnt2[row]);
            const uint16_t* il = g_idx2 + (size_t)row * HID;
            const float* vl = g_val2 + (size_t)row * HID;
            const size_t base = (size_t)row * HID + c;

            ulonglong2 acc = make_ulonglong2(0ull, 0ull);
            if (h > 0 && valid)
                acc = *reinterpret_cast<ulonglong2*>(g_part + base);

            if (ie > ib) {
                int k1 = il[ib] - k0;
                unsigned long long a2 = bcast2(vl[ib]);
                ulonglong2 w = *reinterpret_cast<const ulonglong2*>(
                    &sW2[k1 * NC2 + lane * 4]);
                for (int i = ib; i < ie; i++) {
                    int inext = (i + 1 < ie) ? (i + 1) : (ie - 1);
                    int k2 = il[inext] - k0;
                    unsigned long long an = bcast2(vl[inext]);
                    ulonglong2 wn = *reinterpret_cast<const ulonglong2*>(
                        &sW2[k2 * NC2 + lane * 4]);
                    fma2(acc.x, a2, w.x);
                    fma2(acc.y, a2, w.y);
                    w = wn; a2 = an;
                }
            }

            if (h < 2) {
                if (valid)
                    *reinterpret_cast<ulonglong2*>(g_part + base) = acc;
            } else if (valid) {
                float4 m = *reinterpret_cast<float4*>(mem + base);
                float4 sv = *reinterpret_cast<float4*>(spksum + base);
                float av[4] = { lo32(acc.x), hi32(acc.x), lo32(acc.y), hi32(acc.y) };
                float* mp = &m.x; float* sp = &sv.x;
#pragma unroll
                for (int e = 0; e < 4; e++) {
                    float v = mp[e] + av[e];
                    bool s = (v >= 1.0f);
                    mp[e] = s ? 0.0f : v;
                    if (s) sp[e] += 1.0f;
                }
                *reinterpret_cast<float4*>(mem + base) = m;
                *reinterpret_cast<float4*>(spksum + base) = sv;
            }
        }
    }
}

// Layer 2 dense (mode 0): fused C = A @ W^T ; LIF update. 128x128x16 tiles,
// packed f32x2 FMAs, conflict-free B LDS.128.
__global__ __launch_bounds__(256, 1) void gemm_lif_kernel(
    const float* __restrict__ A, const float* __restrict__ W,
    float* __restrict__ mem, float* __restrict__ spksum,
    int N, int K)
{
    if (g_mode != 0) return;
    __shared__ float As[16][132];
    __shared__ float Bs[16][132];

    const int tid  = threadIdx.x;
    const int row0 = blockIdx.y * 128;
    const int col0 = blockIdx.x * 128;
    const int lr = tid >> 2;
    const int lk = (tid & 3) << 2;
    const int ty = tid >> 4;
    const int tx = tid & 15;

    unsigned long long acc2[8][4];
#pragma unroll
    for (int i = 0; i < 8; i++)
#pragma unroll
        for (int j = 0; j < 4; j++) acc2[i][j] = 0ull;

    for (int k0 = 0; k0 < K; k0 += 16) {
#pragma unroll
        for (int h = 0; h < 2; h++) {
            int r = lr + (h << 6);
            float4 va = *reinterpret_cast<const float4*>(
                A + (size_t)(row0 + r) * K + (k0 + lk));
            As[lk + 0][r] = va.x; As[lk + 1][r] = va.y;
            As[lk + 2][r] = va.z; As[lk + 3][r] = va.w;
            int gn = col0 + r;
            float4 vb = make_float4(0.f, 0.f, 0.f, 0.f);
            if (gn < N)
                vb = *reinterpret_cast<const float4*>(
                    W + (size_t)gn * K + (k0 + lk));
            Bs[lk + 0][r] = vb.x; Bs[lk + 1][r] = vb.y;
            Bs[lk + 2][r] = vb.z; Bs[lk + 3][r] = vb.w;
        }
        __syncthreads();
#pragma unroll
        for (int kk = 0; kk < 16; kk++) {
            float a[8];
            *reinterpret_cast<float4*>(&a[0]) =
                *reinterpret_cast<const float4*>(&As[kk][ty * 8]);
            *reinterpret_cast<float4*>(&a[4]) =
                *reinterpret_cast<const float4*>(&As[kk][ty * 8 + 4]);
            ulonglong2 b01 = *reinterpret_cast<const ulonglong2*>(&Bs[kk][tx * 4]);
            ulonglong2 b23 = *reinterpret_cast<const ulonglong2*>(&Bs[kk][64 + tx * 4]);
#pragma unroll
            for (int i = 0; i < 8; i++) {
                unsigned long long a2 = bcast2(a[i]);
                fma2(acc2[i][0], a2, b01.x);
                fma2(acc2[i][1], a2, b01.y);
                fma2(acc2[i][2], a2, b23.x);
                fma2(acc2[i][3], a2, b23.y);
            }
        }
        __syncthreads();
    }

#pragma unroll
    for (int i = 0; i < 8; i++) {
        int r = row0 + ty * 8 + i;
#pragma unroll
        for (int hb = 0; hb < 2; hb++) {
            int cbase = col0 + hb * 64 + tx * 4;
            if (cbase < N) {
                float av[4] = { lo32(acc2[i][2 * hb]),     hi32(acc2[i][2 * hb]),
                                lo32(acc2[i][2 * hb + 1]), hi32(acc2[i][2 * hb + 1]) };
                size_t idx = (size_t)r * N + cbase;
                float4 m = *reinterpret_cast<float4*>(mem + idx);
                float4 sv = *reinterpret_cast<float4*>(spksum + idx);
                float* mp = &m.x; float* sp = &sv.x;
#pragma unroll
                for (int e = 0; e < 4; e++) {
                    float v = mp[e] + av[e];
                    bool s = (v >= 1.0f);
                    mp[e] = s ? 0.0f : v;
                    if (s) sp[e] += 1.0f;
                }
                *reinterpret_cast<float4*>(mem + idx) = m;
                *reinterpret_cast<float4*>(spksum + idx) = sv;
            }
        }
    }
}

// Layer 3: one warp per batch row, W3 (10 x 1200) cached in SMEM.
__global__ __launch_bounds__(256) void layer3_kernel(
    const float* __restrict__ A /* g_sum2 */, const float* __restrict__ W3,
    float* __restrict__ out, int last)
{
    __shared__ float W3s[DOUT * HID];
    for (int i = threadIdx.x; i < DOUT * HID; i += blockDim.x)
        W3s[i] = W3[i];
    __syncthreads();

    int warp = (blockIdx.x * blockDim.x + threadIdx.x) >> 5;
    int lane = threadIdx.x & 31;
    if (warp >= BATCH) return;

    const float* a = A + (size_t)warp * HID;
    float acc[DOUT];
#pragma unroll
    for (int n = 0; n < DOUT; n++) acc[n] = 0.f;

    for (int k = lane; k < HID; k += 32) {
        float av = a[k];
#pragma unroll
        for (int n = 0; n < DOUT; n++)
            acc[n] = fmaf(av, W3s[n * HID + k], acc[n]);
    }
#pragma unroll
    for (int n = 0; n < DOUT; n++) {
#pragma unroll
        for (int off = 16; off; off >>= 1)
            acc[n] += __shfl_xor_sync(0xffffffffu, acc[n], off);
    }
    if (lane < DOUT) {
        size_t idx = (size_t)warp * DOUT + lane;
        float m = g_mem3[idx] + acc[lane];
        bool s = (m >= 1.0f);
        g_mem3[idx] = s ? 0.0f : m;
        float s3 = g_sum3[idx] + (s ? 1.0f : 0.0f);
        g_sum3[idx] = s3;
        if (last) out[idx] = s3 / 35.0f;
    }
}

// ---------------- host ----------------
extern "C" void kernel_launch(void* const* d_in, const int* in_sizes, int n_in,
                              void* d_out, int out_size)
{
    const float* x  = (const float*)d_in[0];
    const float* W1 = (const float*)d_in[1];
    const float* W2 = (const float*)d_in[2];
    const float* W3 = (const float*)d_in[3];
    float* out = (float*)d_out;

    float *mem1, *sum1, *mem2, *sum2;
    cudaGetSymbolAddress((void**)&mem1, g_mem1);
    cudaGetSymbolAddress((void**)&sum1, g_sum1);
    cudaGetSymbolAddress((void**)&mem2, g_mem2);
    cudaGetSymbolAddress((void**)&sum2, g_sum2);

    const int l1_smem = KH1 * NC1 * sizeof(float);   // 200704 B
    const int l2_smem = KS2 * NC2 * sizeof(float);   // 204800 B
    cudaFuncSetAttribute(layer1_sparse_kernel,
                         cudaFuncAttributeMaxDynamicSharedMemorySize, l1_smem);
    cudaFuncSetAttribute(layer2_sparse_kernel,
                         cudaFuncAttributeMaxDynamicSharedMemorySize, l2_smem);

    zero_state_kernel<<<512, 256>>>();
    transpose_w1_kernel<<<(DIN * HID + 255) / 256, 256>>>(W1);
    transpose_w2_kernel<<<(HID * HID + 255) / 256, 256>>>(W2);

    const dim3 l1_grid(BATCH / 512, (HID + NC1 - 1) / NC1);  // (16, 10)
    const dim3 l2_grid(BATCH / 512, (HID + NC2 - 1) / NC2);  // (16, 10)
    const dim3 gemm_grid((HID + 127) / 128, BATCH / 128);    // (10, 64)

    for (int t = 0; t < TSTEPS; t++) {
        uint32_t kt0, kt1;
        threefry2x32(0u, 42u, 0u, (uint32_t)t, kt0, kt1);

        spike_compact_kernel<<<BATCH / 8, 256>>>(x, kt0, kt1);
        layer1_sparse_kernel<<<l1_grid, 512, l1_smem>>>(mem1, sum1);
        compact2_kernel<<<BATCH / 8, 256>>>();
        set_mode_kernel<<<1, 1>>>();
        layer2_sparse_kernel<<<l2_grid, 512, l2_smem>>>(mem2, sum2);
        gemm_lif_kernel<<<gemm_grid, 256>>>(sum1, W2, mem2, sum2, HID, HID);
        layer3_kernel<<<BATCH / 8, 256>>>(sum2, W3, out, (t == TSTEPS - 1) ? 1 : 0);
    }
}

// round 16
// speedup vs baseline: 2.0753x; 2.0753x over previous
#include <cuda_runtime.h>
#include <cstdint>
#include <cstddef>

#define BATCH  8192
#define DIN    784
#define HID    1200
#define DOUT   10
#define TSTEPS 35

#define NC1    64
#define NC2    64
#define KHALF  600
// sparse layer-2 selected when total nnz < BATCH * NNZ_THRESH_PER_ROW
#define NNZ_THRESH_PER_ROW 350

// ---------------- device state (no allocs allowed) ----------------
__device__ float g_mem1[(size_t)BATCH * HID];
__device__ float g_sum1[(size_t)BATCH * HID];
__device__ float g_mem2[(size_t)BATCH * HID];
__device__ float g_sum2[(size_t)BATCH * HID];
__device__ float g_mem3[(size_t)BATCH * DOUT];
__device__ float g_sum3[(size_t)BATCH * DOUT];
__device__ float g_W1T[(size_t)DIN * HID];            // W1 transposed: [k][n]
__device__ float g_W2T[(size_t)HID * HID];            // W2 transposed: [k][n]
__device__ uint16_t g_idx[(size_t)BATCH * DIN];       // layer1 spike indices (ascending)
__device__ int g_cnt[BATCH];
__device__ uint16_t g_idx2[(size_t)BATCH * HID];      // layer2 nonzero indices (ascending)
__device__ float g_val2[(size_t)BATCH * HID];         // layer2 nonzero values
__device__ int g_cnt2[BATCH];
__device__ int g_cnt2lo[BATCH];                       // count with k < KHALF
__device__ float g_part[(size_t)BATCH * HID];         // layer2 partial accumulators
__device__ int g_nnz_total;
__device__ int g_mode;                                // 1 = sparse layer2, 0 = dense

// ---------------- packed f32x2 helpers ----------------
__device__ __forceinline__ void fma2(unsigned long long& acc,
                                     unsigned long long a2, unsigned long long b2) {
    asm("fma.rn.f32x2 %0, %1, %2, %0;" : "+l"(acc) : "l"(a2), "l"(b2));
}
__device__ __forceinline__ unsigned long long bcast2(float v) {
    unsigned long long r;
    asm("mov.b64 %0, {%1, %1};" : "=l"(r) : "r"(__float_as_uint(v)));
    return r;
}
__device__ __forceinline__ float lo32(unsigned long long p) {
    return __uint_as_float((uint32_t)p);
}
__device__ __forceinline__ float hi32(unsigned long long p) {
    return __uint_as_float((uint32_t)(p >> 32));
}

// ---------------- Threefry-2x32 (exact JAX semantics) ----------------
__host__ __device__ __forceinline__ uint32_t rotl32(uint32_t v, int r) {
#ifdef __CUDA_ARCH__
    return __funnelshift_l(v, v, r);
#else
    return (v << r) | (v >> (32 - r));
#endif
}

__host__ __device__ __forceinline__ void threefry2x32(
    uint32_t k0, uint32_t k1, uint32_t x0, uint32_t x1,
    uint32_t& o0, uint32_t& o1)
{
    uint32_t ks2 = k0 ^ k1 ^ 0x1BD11BDAu;
    x0 += k0; x1 += k1;
#define TF_R(r) { x0 += x1; x1 = rotl32(x1, (r)); x1 ^= x0; }
    TF_R(13) TF_R(15) TF_R(26) TF_R(6)
    x0 += k1;  x1 += ks2 + 1u;
    TF_R(17) TF_R(29) TF_R(16) TF_R(24)
    x0 += ks2; x1 += k0 + 2u;
    TF_R(13) TF_R(15) TF_R(26) TF_R(6)
    x0 += k0;  x1 += k1 + 3u;
    TF_R(17) TF_R(29) TF_R(16) TF_R(24)
    x0 += k1;  x1 += ks2 + 4u;
    TF_R(13) TF_R(15) TF_R(26) TF_R(6)
    x0 += ks2; x1 += k0 + 5u;
#undef TF_R
    o0 = x0; o1 = x1;
}

// ---------------- kernels ----------------
__global__ void zero_state_kernel() {
    size_t i = (size_t)blockIdx.x * blockDim.x + threadIdx.x;
    size_t stride = (size_t)gridDim.x * blockDim.x;
    size_t total = (size_t)BATCH * HID;
    for (size_t p = i; p < total; p += stride) {
        g_mem1[p] = 0.f; g_sum1[p] = 0.f;
        g_mem2[p] = 0.f; g_sum2[p] = 0.f;
    }
    if (i < (size_t)BATCH * DOUT) { g_mem3[i] = 0.f; g_sum3[i] = 0.f; }
    if (i == 0) { g_nnz_total = 0; g_mode = 0; }
}

__global__ void transpose_w1_kernel(const float* __restrict__ W1) {
    int idx = blockIdx.x * blockDim.x + threadIdx.x;
    if (idx >= DIN * HID) return;
    int k = idx / HID, n = idx - k * HID;
    g_W1T[idx] = W1[(size_t)n * DIN + k];
}

__global__ void transpose_w2_kernel(const float* __restrict__ W2) {
    int idx = blockIdx.x * blockDim.x + threadIdx.x;
    if (idx >= HID * HID) return;
    int k = idx / HID, n = idx - k * HID;
    g_W2T[idx] = W2[(size_t)n * HID + k];
}

// Spike gen + per-row compaction (ascending k). One warp per batch row.
// JAX threefry_partitionable bits: counter (0, i); bits = out0 ^ out1
__global__ __launch_bounds__(256) void spike_compact_kernel(
    const float* __restrict__ x, uint32_t kt0, uint32_t kt1)
{
    int warp = (blockIdx.x * blockDim.x + threadIdx.x) >> 5;
    int lane = threadIdx.x & 31;
    if (warp >= BATCH) return;
    const float* xr = x + (size_t)warp * DIN;
    uint16_t* outp = g_idx + (size_t)warp * DIN;
    int cnt = 0;
    for (int base = 0; base < DIN; base += 32) {
        int k = base + lane;
        bool p = false;
        if (k < DIN) {
            uint32_t i = (uint32_t)(warp * DIN + k);
            uint32_t y0, y1;
            threefry2x32(kt0, kt1, 0u, i, y0, y1);
            uint32_t bits = y0 ^ y1;
            uint32_t fb = (bits >> 9) | 0x3f800000u;
            float u = __uint_as_float(fb) - 1.0f;
            p = (u * 5.0f <= xr[k]);
        }
        unsigned mask = __ballot_sync(0xffffffffu, p);
        if (p) outp[cnt + __popc(mask & ((1u << lane) - 1))] = (uint16_t)k;
        cnt += __popc(mask);
    }
    if (lane == 0) g_cnt[warp] = cnt;
}

// Layer 1 sparse, warp-per-row broadcast layout (bit-exact ascending-k chain).
// Inner loop batches 4 nonzeros per iteration: one ushort4 index load feeds
// 4x (LDS.64 + fma2). Chain order unchanged.
__global__ __launch_bounds__(512, 1) void layer1_sparse_kernel(
    float* __restrict__ mem, float* __restrict__ spksum)
{
    extern __shared__ float sW[];   // DIN * NC1 floats
    const int tid = threadIdx.x;
    const int c0 = blockIdx.y * NC1;

    for (int idx = tid; idx < DIN * (NC1 / 4); idx += 512) {
        int k = idx / (NC1 / 4), q = idx - k * (NC1 / 4);
        int c = c0 + q * 4;
        float4 v = make_float4(0.f, 0.f, 0.f, 0.f);
        if (c + 3 < HID)
            v = *reinterpret_cast<const float4*>(&g_W1T[(size_t)k * HID + c]);
        *reinterpret_cast<float4*>(&sW[k * NC1 + q * 4]) = v;
    }
    __syncthreads();

    const int wrp  = tid >> 5;
    const int lane = tid & 31;
    const int c = c0 + lane * 2;
    const bool valid = (c < HID);
    const unsigned long long ones = 0x3f8000003f800000ull;

    for (int rl = 0; rl < 32; rl++) {
        const int row = blockIdx.x * 512 + wrp * 32 + rl;
        const int n = g_cnt[row];
        const uint16_t* il = g_idx + (size_t)row * DIN;   // 8B-aligned (784*2)

        unsigned long long acc = 0ull;
        int i = 0;
        for (; i + 4 <= n; i += 4) {
            ushort4 k4 = *reinterpret_cast<const ushort4*>(il + i);
            unsigned long long w0 = *reinterpret_cast<const unsigned long long*>(
                &sW[k4.x * NC1 + lane * 2]);
            unsigned long long w1 = *reinterpret_cast<const unsigned long long*>(
                &sW[k4.y * NC1 + lane * 2]);
            unsigned long long w2 = *reinterpret_cast<const unsigned long long*>(
                &sW[k4.z * NC1 + lane * 2]);
            unsigned long long w3 = *reinterpret_cast<const unsigned long long*>(
                &sW[k4.w * NC1 + lane * 2]);
            fma2(acc, w0, ones);
            fma2(acc, w1, ones);
            fma2(acc, w2, ones);
            fma2(acc, w3, ones);
        }
        for (; i < n; i++) {
            unsigned long long w = *reinterpret_cast<const unsigned long long*>(
                &sW[il[i] * NC1 + lane * 2]);
            fma2(acc, w, ones);
        }

        if (valid) {
            size_t base = (size_t)row * HID + c;
            float2 m = *reinterpret_cast<float2*>(mem + base);
            float2 sv = *reinterpret_cast<float2*>(spksum + base);
            float v0 = m.x + lo32(acc);
            float v1 = m.y + hi32(acc);
            bool s0 = (v0 >= 1.0f);
            bool s1 = (v1 >= 1.0f);
            m.x = s0 ? 0.0f : v0;
            m.y = s1 ? 0.0f : v1;
            if (s0) sv.x += 1.0f;
            if (s1) sv.y += 1.0f;
            *reinterpret_cast<float2*>(mem + base) = m;
            *reinterpret_cast<float2*>(spksum + base) = sv;
        }
    }
}

// Compact nonzeros of sum1 per row (ascending k) + global nnz tally.
__global__ __launch_bounds__(256) void compact2_kernel() {
    int warp = (blockIdx.x * blockDim.x + threadIdx.x) >> 5;
    int lane = threadIdx.x & 31;
    if (warp >= BATCH) return;
    const float* sr = g_sum1 + (size_t)warp * HID;
    uint16_t* outi = g_idx2 + (size_t)warp * HID;
    float* outv = g_val2 + (size_t)warp * HID;
    int cnt = 0, cntlo = 0;
    for (int base = 0; base < HID; base += 32) {
        int k = base + lane;
        float v = (k < HID) ? sr[k] : 0.f;
        bool p = (v != 0.f);
        unsigned mask = __ballot_sync(0xffffffffu, p);
        if (p) {
            int pos = cnt + __popc(mask & ((1u << lane) - 1));
            outi[pos] = (uint16_t)k;
            outv[pos] = v;
        }
        cnt += __popc(mask);
        unsigned lomask = (base + 32 <= KHALF) ? 0xffffffffu
                        : (base >= KHALF ? 0u : ((1u << (KHALF - base)) - 1u));
        cntlo += __popc(mask & lomask);
    }
    if (lane == 0) {
        g_cnt2[warp] = cnt;
        g_cnt2lo[warp] = cntlo;
        atomicAdd(&g_nnz_total, cnt);
    }
}

// Choose layer-2 path from total density; reset tally for next step.
__global__ void set_mode_kernel() {
    g_mode = (g_nnz_total < BATCH * NNZ_THRESH_PER_ROW) ? 1 : 0;
    g_nnz_total = 0;
}

// Layer 2 sparse (mode 1): warp-per-row broadcast, skips exact zeros in
// ascending k -> bit-identical chain to the dense kernel. K in two smem
// halves; chain crosses halves via g_part (bits unchanged through memory).
// Inner loop batches 4 nonzeros (ushort4 + float4) after an alignment head.
__global__ __launch_bounds__(512, 1) void layer2_sparse_kernel(
    float* __restrict__ mem, float* __restrict__ spksum)
{
    if (g_mode != 1) return;
    extern __shared__ float sW2[];   // KHALF * NC2 floats
    const int tid = threadIdx.x;
    const int c0 = blockIdx.y * NC2;
    const int wrp  = tid >> 5;
    const int lane = tid & 31;
    const int c = c0 + lane * 2;
    const bool valid = (c < HID);

    for (int h = 0; h < 2; h++) {
        const int k0 = h * KHALF;
        __syncthreads();   // previous half fully consumed before restage
        for (int idx = tid; idx < KHALF * (NC2 / 4); idx += 512) {
            int k = idx / (NC2 / 4), q = idx - k * (NC2 / 4);
            int cc = c0 + q * 4;
            float4 v = make_float4(0.f, 0.f, 0.f, 0.f);
            if (cc + 3 < HID)
                v = *reinterpret_cast<const float4*>(
                    &g_W2T[(size_t)(k0 + k) * HID + cc]);
            *reinterpret_cast<float4*>(&sW2[k * NC2 + q * 4]) = v;
        }
        __syncthreads();

        for (int rl = 0; rl < 32; rl++) {
            const int row = blockIdx.x * 512 + wrp * 32 + rl;
            const int ib = h ? g_cnt2lo[row] : 0;
            const int ie = h ? g_cnt2[row] : g_cnt2lo[row];
            const uint16_t* il = g_idx2 + (size_t)row * HID;  // 8B-aligned (1200*2)
            const float* vl = g_val2 + (size_t)row * HID;     // 16B-aligned (1200*4)
            const size_t base = (size_t)row * HID + c;

            unsigned long long acc = 0ull;
            if (h == 1 && valid)
                acc = *reinterpret_cast<unsigned long long*>(g_part + base);

            int i = ib;
            // scalar head to reach 4-alignment (preserves ascending order)
            for (; i < ie && (i & 3); i++) {
                unsigned long long a2 = bcast2(vl[i]);
                unsigned long long w = *reinterpret_cast<const unsigned long long*>(
                    &sW2[(il[i] - k0) * NC2 + lane * 2]);
                fma2(acc, a2, w);
            }
            for (; i + 4 <= ie; i += 4) {
                ushort4 k4 = *reinterpret_cast<const ushort4*>(il + i);
                float4 v4 = *reinterpret_cast<const float4*>(vl + i);
                unsigned long long w0 = *reinterpret_cast<const unsigned long long*>(
                    &sW2[(k4.x - k0) * NC2 + lane * 2]);
                unsigned long long w1 = *reinterpret_cast<const unsigned long long*>(
                    &sW2[(k4.y - k0) * NC2 + lane * 2]);
                unsigned long long w2 = *reinterpret_cast<const unsigned long long*>(
                    &sW2[(k4.z - k0) * NC2 + lane * 2]);
                unsigned long long w3 = *reinterpret_cast<const unsigned long long*>(
                    &sW2[(k4.w - k0) * NC2 + lane * 2]);
                fma2(acc, bcast2(v4.x), w0);
                fma2(acc, bcast2(v4.y), w1);
                fma2(acc, bcast2(v4.z), w2);
                fma2(acc, bcast2(v4.w), w3);
            }
            for (; i < ie; i++) {
                unsigned long long a2 = bcast2(vl[i]);
                unsigned long long w = *reinterpret_cast<const unsigned long long*>(
                    &sW2[(il[i] - k0) * NC2 + lane * 2]);
                fma2(acc, a2, w);
            }

            if (h == 0) {
                if (valid)
                    *reinterpret_cast<unsigned long long*>(g_part + base) = acc;
            } else if (valid) {
                float2 m = *reinterpret_cast<float2*>(mem + base);
                float2 sv = *reinterpret_cast<float2*>(spksum + base);
                float v0 = m.x + lo32(acc);
                float v1 = m.y + hi32(acc);
                bool s0 = (v0 >= 1.0f);
                bool s1 = (v1 >= 1.0f);
                m.x = s0 ? 0.0f : v0;
                m.y = s1 ? 0.0f : v1;
                if (s0) sv.x += 1.0f;
                if (s1) sv.y += 1.0f;
                *reinterpret_cast<float2*>(mem + base) = m;
                *reinterpret_cast<float2*>(spksum + base) = sv;
            }
        }
    }
}

// Layer 2 dense (mode 0): fused C = A @ W^T ; LIF update. 128x128x16 tiles,
// packed f32x2 FMAs, conflict-free B LDS.128.
__global__ __launch_bounds__(256, 1) void gemm_lif_kernel(
    const float* __restrict__ A, const float* __restrict__ W,
    float* __restrict__ mem, float* __restrict__ spksum,
    int N, int K)
{
    if (g_mode != 0) return;
    __shared__ float As[16][132];
    __shared__ float Bs[16][132];

    const int tid  = threadIdx.x;
    const int row0 = blockIdx.y * 128;
    const int col0 = blockIdx.x * 128;
    const int lr = tid >> 2;
    const int lk = (tid & 3) << 2;
    const int ty = tid >> 4;
    const int tx = tid & 15;

    unsigned long long acc2[8][4];
#pragma unroll
    for (int i = 0; i < 8; i++)
#pragma unroll
        for (int j = 0; j < 4; j++) acc2[i][j] = 0ull;

    for (int k0 = 0; k0 < K; k0 += 16) {
#pragma unroll
        for (int h = 0; h < 2; h++) {
            int r = lr + (h << 6);
            float4 va = *reinterpret_cast<const float4*>(
                A + (size_t)(row0 + r) * K + (k0 + lk));
            As[lk + 0][r] = va.x; As[lk + 1][r] = va.y;
            As[lk + 2][r] = va.z; As[lk + 3][r] = va.w;
            int gn = col0 + r;
            float4 vb = make_float4(0.f, 0.f, 0.f, 0.f);
            if (gn < N)
                vb = *reinterpret_cast<const float4*>(
                    W + (size_t)gn * K + (k0 + lk));
            Bs[lk + 0][r] = vb.x; Bs[lk + 1][r] = vb.y;
            Bs[lk + 2][r] = vb.z; Bs[lk + 3][r] = vb.w;
        }
        __syncthreads();
#pragma unroll
        for (int kk = 0; kk < 16; kk++) {
            float a[8];
            *reinterpret_cast<float4*>(&a[0]) =
                *reinterpret_cast<const float4*>(&As[kk][ty * 8]);
            *reinterpret_cast<float4*>(&a[4]) =
                *reinterpret_cast<const float4*>(&As[kk][ty * 8 + 4]);
            ulonglong2 b01 = *reinterpret_cast<const ulonglong2*>(&Bs[kk][tx * 4]);
            ulonglong2 b23 = *reinterpret_cast<const ulonglong2*>(&Bs[kk][64 + tx * 4]);
#pragma unroll
            for (int i = 0; i < 8; i++) {
                unsigned long long a2 = bcast2(a[i]);
                fma2(acc2[i][0], a2, b01.x);
                fma2(acc2[i][1], a2, b01.y);
                fma2(acc2[i][2], a2, b23.x);
                fma2(acc2[i][3], a2, b23.y);
            }
        }
        __syncthreads();
    }

#pragma unroll
    for (int i = 0; i < 8; i++) {
        int r = row0 + ty * 8 + i;
#pragma unroll
        for (int hb = 0; hb < 2; hb++) {
            int cbase = col0 + hb * 64 + tx * 4;
            if (cbase < N) {
                float av[4] = { lo32(acc2[i][2 * hb]),     hi32(acc2[i][2 * hb]),
                                lo32(acc2[i][2 * hb + 1]), hi32(acc2[i][2 * hb + 1]) };
                size_t idx = (size_t)r * N + cbase;
                float4 m = *reinterpret_cast<float4*>(mem + idx);
                float4 sv = *reinterpret_cast<float4*>(spksum + idx);
                float* mp = &m.x; float* sp = &sv.x;
#pragma unroll
                for (int e = 0; e < 4; e++) {
                    float v = mp[e] + av[e];
                    bool s = (v >= 1.0f);
                    mp[e] = s ? 0.0f : v;
                    if (s) sp[e] += 1.0f;
                }
                *reinterpret_cast<float4*>(mem + idx) = m;
                *reinterpret_cast<float4*>(spksum + idx) = sv;
            }
        }
    }
}

// Layer 3: one warp per batch row, W3 (10 x 1200) cached in SMEM.
__global__ __launch_bounds__(256) void layer3_kernel(
    const float* __restrict__ A /* g_sum2 */, const float* __restrict__ W3,
    float* __restrict__ out, int last)
{
    __shared__ float W3s[DOUT * HID];
    for (int i = threadIdx.x; i < DOUT * HID; i += blockDim.x)
        W3s[i] = W3[i];
    __syncthreads();

    int warp = (blockIdx.x * blockDim.x + threadIdx.x) >> 5;
    int lane = threadIdx.x & 31;
    if (warp >= BATCH) return;

    const float* a = A + (size_t)warp * HID;
    float acc[DOUT];
#pragma unroll
    for (int n = 0; n < DOUT; n++) acc[n] = 0.f;

    for (int k = lane; k < HID; k += 32) {
        float av = a[k];
#pragma unroll
        for (int n = 0; n < DOUT; n++)
            acc[n] = fmaf(av, W3s[n * HID + k], acc[n]);
    }
#pragma unroll
    for (int n = 0; n < DOUT; n++) {
#pragma unroll
        for (int off = 16; off; off >>= 1)
            acc[n] += __shfl_xor_sync(0xffffffffu, acc[n], off);
    }
    if (lane < DOUT) {
        size_t idx = (size_t)warp * DOUT + lane;
        float m = g_mem3[idx] + acc[lane];
        bool s = (m >= 1.0f);
        g_mem3[idx] = s ? 0.0f : m;
        float s3 = g_sum3[idx] + (s ? 1.0f : 0.0f);
        g_sum3[idx] = s3;
        if (last) out[idx] = s3 / 35.0f;   // match reference: exact fp32 divide
    }
}

// ---------------- host ----------------
extern "C" void kernel_launch(void* const* d_in, const int* in_sizes, int n_in,
                              void* d_out, int out_size)
{
    const float* x  = (const float*)d_in[0];
    const float* W1 = (const float*)d_in[1];
    const float* W2 = (const float*)d_in[2];
    const float* W3 = (const float*)d_in[3];
    float* out = (float*)d_out;

    float *mem1, *sum1, *mem2, *sum2;
    cudaGetSymbolAddress((void**)&mem1, g_mem1);
    cudaGetSymbolAddress((void**)&sum1, g_sum1);
    cudaGetSymbolAddress((void**)&mem2, g_mem2);
    cudaGetSymbolAddress((void**)&sum2, g_sum2);

    const int l1_smem = DIN * NC1 * sizeof(float);     // 200704 B
    const int l2_smem = KHALF * NC2 * sizeof(float);   // 153600 B
    cudaFuncSetAttribute(layer1_sparse_kernel,
                         cudaFuncAttributeMaxDynamicSharedMemorySize, l1_smem);
    cudaFuncSetAttribute(layer2_sparse_kernel,
                         cudaFuncAttributeMaxDynamicSharedMemorySize, l2_smem);

    zero_state_kernel<<<512, 256>>>();
    transpose_w1_kernel<<<(DIN * HID + 255) / 256, 256>>>(W1);
    transpose_w2_kernel<<<(HID * HID + 255) / 256, 256>>>(W2);

    const dim3 l1_grid(BATCH / 512, (HID + NC1 - 1) / NC1);  // (16, 19)
    const dim3 l2_grid(BATCH / 512, (HID + NC2 - 1) / NC2);  // (16, 19)
    const dim3 gemm_grid((HID + 127) / 128, BATCH / 128);    // (10, 64)

    for (int t = 0; t < TSTEPS; t++) {
        // kt = fold_in(key(42), t) = threefry2x32((0,42), (0,t))
        uint32_t kt0, kt1;
        threefry2x32(0u, 42u, 0u, (uint32_t)t, kt0, kt1);

        spike_compact_kernel<<<BATCH / 8, 256>>>(x, kt0, kt1);
        layer1_sparse_kernel<<<l1_grid, 512, l1_smem>>>(mem1, sum1);
        compact2_kernel<<<BATCH / 8, 256>>>();
        set_mode_kernel<<<1, 1>>>();
        layer2_sparse_kernel<<<l2_grid, 512, l2_smem>>>(mem2, sum2);
        gemm_lif_kernel<<<gemm_grid, 256>>>(sum1, W2, mem2, sum2, HID, HID);
        layer3_kernel<<<BATCH / 8, 256>>>(sum2, W3, out, (t == TSTEPS - 1) ? 1 : 0);
    }
}